// round 14
// baseline (speedup 1.0000x reference)
#include <cuda_runtime.h>
#include <cuda_bf16.h>
#include <cuda_fp16.h>
#include <cstdint>

#define SEQ   2048
#define HDIM  4096
#define NH    32
#define NKV   8
#define HD    128

// ---------------------------------------------------------------------------
// Scratch (__device__ globals; no cudaMalloc allowed)
// ---------------------------------------------------------------------------
__device__ __half g_hq16[SEQ * HDIM], g_hk16[SEQ * HDIM], g_hv16[SEQ * HDIM];
__device__ __half g_wq16[4096 * 4096], g_wk16[1024 * 4096], g_wv16[1024 * 4096];
__device__ __half g_wo16[4096 * 4096];
__device__ __half g_ao16[SEQ * HDIM];
__device__ float g_Q[SEQ * NH * HD];
__device__ float g_K[SEQ * NKV * HD];
__device__ float g_V[SEQ * NKV * HD];
__device__ float g_A[SEQ * NH * HD];
__device__ __half g_Q16[SEQ * NH * HD];
__device__ __half g_K16[SEQ * NKV * HD];
__device__ __half g_V16[SEQ * NKV * HD];

// ---------------------------------------------------------------------------
// PTX helpers (baseline PTX only; works on plain sm_103 target)
// ---------------------------------------------------------------------------
static __device__ __forceinline__ uint32_t smem_u32(const void* p) {
  uint32_t a;
  asm("{ .reg .u64 t; cvta.to.shared.u64 t, %1; cvt.u32.u64 %0, t; }"
      : "=r"(a) : "l"(p));
  return a;
}

#define CP_ASYNC16(dst, src) \
  asm volatile("cp.async.cg.shared.global [%0], [%1], 16;" :: "r"(dst), "l"(src))
#define CP_COMMIT()   asm volatile("cp.async.commit_group;" ::: "memory")
#define CP_WAIT(n)    asm volatile("cp.async.wait_group %0;" :: "n"(n) : "memory")

static __device__ __forceinline__ void ldsm_x4(uint32_t* r, uint32_t addr) {
  asm volatile("ldmatrix.sync.aligned.m8n8.x4.shared.b16 {%0,%1,%2,%3}, [%4];"
               : "=r"(r[0]), "=r"(r[1]), "=r"(r[2]), "=r"(r[3]) : "r"(addr));
}
static __device__ __forceinline__ void ldsm_x4_t(uint32_t* r, uint32_t addr) {
  asm volatile("ldmatrix.sync.aligned.m8n8.x4.trans.shared.b16 {%0,%1,%2,%3}, [%4];"
               : "=r"(r[0]), "=r"(r[1]), "=r"(r[2]), "=r"(r[3]) : "r"(addr));
}

static __device__ __forceinline__ void mma_f16(float* d, const uint32_t* a,
                                               const uint32_t* b) {
  asm volatile(
      "mma.sync.aligned.m16n8k16.row.col.f32.f16.f16.f32 "
      "{%0,%1,%2,%3}, {%4,%5,%6,%7}, {%8,%9}, {%0,%1,%2,%3};"
      : "+f"(d[0]), "+f"(d[1]), "+f"(d[2]), "+f"(d[3])
      : "r"(a[0]), "r"(a[1]), "r"(a[2]), "r"(a[3]), "r"(b[0]), "r"(b[1]));
}

static __device__ __forceinline__ uint32_t pkhf(float a, float b) {
  __half2 t = __floats2half2_rn(a, b);
  return *(uint32_t*)&t;
}

// ---------------------------------------------------------------------------
// Fused 3-way gather + fp16 convert (QKV path): per-row smem staging.
// ---------------------------------------------------------------------------
__global__ void __launch_bounds__(256) gather3_convert_kernel(
    const float* __restrict__ in,
    const int* __restrict__ qi, const int* __restrict__ ki,
    const int* __restrict__ vi,
    __half* __restrict__ q16, __half* __restrict__ k16,
    __half* __restrict__ v16) {
  __shared__ __align__(16) float row[HDIM];
  const int t = blockIdx.x;
  const float* src = in + (size_t)t * HDIM;
#pragma unroll
  for (int i = 0; i < 4; i++) {
    int e = (i * 256 + threadIdx.x) * 4;
    *(float4*)&row[e] = *(const float4*)&src[e];
  }
  __syncthreads();
  const size_t base = (size_t)t * HDIM;
#pragma unroll
  for (int i = 0; i < 16; i++) {
    int c = i * 256 + threadIdx.x;
    q16[base + c] = __float2half_rn(row[qi[c]]);
    k16[base + c] = __float2half_rn(row[ki[c]]);
    v16[base + c] = __float2half_rn(row[vi[c]]);
  }
}

// Single-perm fp16 variant (O path)
__global__ void __launch_bounds__(256) gather1_convert_kernel(
    const float* __restrict__ in, const int* __restrict__ idx,
    __half* __restrict__ o16) {
  __shared__ __align__(16) float row[HDIM];
  const int t = blockIdx.x;
  const float* src = in + (size_t)t * HDIM;
#pragma unroll
  for (int i = 0; i < 4; i++) {
    int e = (i * 256 + threadIdx.x) * 4;
    *(float4*)&row[e] = *(const float4*)&src[e];
  }
  __syncthreads();
  const size_t base = (size_t)t * HDIM;
#pragma unroll
  for (int i = 0; i < 16; i++) {
    int c = i * 256 + threadIdx.x;
    o16[base + c] = __float2half_rn(row[idx[c]]);
  }
}

// ---------------------------------------------------------------------------
// All four weight converts in ONE launch. grid = (4, 10240); row-range select.
// ---------------------------------------------------------------------------
__global__ void __launch_bounds__(256) wconvert_all_kernel(
    const float* __restrict__ Wq, const float* __restrict__ Wk,
    const float* __restrict__ Wv, const float* __restrict__ Wo,
    const int* __restrict__ qrow, const int* __restrict__ krow,
    const int* __restrict__ vrow, const int* __restrict__ orow,
    __half* __restrict__ oq, __half* __restrict__ ok,
    __half* __restrict__ ov, __half* __restrict__ oo) {
  int j = blockIdx.y;
  const float* W; const int* ridx; __half* out; int jj;
  if (j < 4096)      { W = Wq; ridx = qrow; out = oq; jj = j; }
  else if (j < 5120) { W = Wk; ridx = krow; out = ok; jj = j - 4096; }
  else if (j < 6144) { W = Wv; ridx = vrow; out = ov; jj = j - 5120; }
  else               { W = Wo; ridx = orow; out = oo; jj = j - 6144; }
  int c4 = (blockIdx.x * 256 + threadIdx.x) * 4;
  float4 v = *(const float4*)&W[(size_t)ridx[jj] * HDIM + c4];
  uint2 s;
  s.x = pkhf(v.x, v.y); s.y = pkhf(v.z, v.w);
  *(uint2*)&out[(size_t)jj * HDIM + c4] = s;
}

// ---------------------------------------------------------------------------
// Single-pass fp16 GEMM: C = A @ B^T, fp32 accum.
// BM=BN=128, BK=32, 8 warps x (32x64). 4-stage cp.async ring, 1 sync/iter.
// blockIdx.z selects between two problem sets (K/V fusion).
// ---------------------------------------------------------------------------
#define STAGE16_B 20480
#define NSTAGE 4
#define GEMM16_SMEM (NSTAGE * STAGE16_B)

__global__ void __launch_bounds__(256) gemm16_mma_kernel(
    const __half* A_, const __half* B_, float* C_, int Ntot,
    const __half* A2, const __half* B2, float* C2) {
  const __half* A = A_; const __half* B = B_; float* C = C_;
  if (blockIdx.z == 1) { A = A2; B = B2; C = C2; }

  extern __shared__ __align__(1024) char smem[];
  uint32_t sb = smem_u32(smem);
  const int tid = threadIdx.x, wid = tid >> 5, lane = tid & 31;
  const int row0 = blockIdx.x * 128, col0 = blockIdx.y * 128;

  const __half* ld_src[4];
  uint32_t ld_dst[4];
#pragma unroll
  for (int i = 0; i < 4; i++) {
    int t = i * 256 + tid;
    int mat = t >> 9, r = (t >> 2) & 127, c = t & 3;
    const __half* base = (mat == 0) ? A + (size_t)row0 * 4096
                                    : B + (size_t)col0 * 4096;
    ld_src[i] = base + (size_t)r * 4096 + c * 8;
    ld_dst[i] = (uint32_t)(mat * 10240 + r * 80 + c * 16);
  }

  const int m0 = (wid & 3) * 32, n0 = (wid >> 2) * 64;
  const uint32_t a_lrow = (lane & 7) + ((lane >> 3) & 1) * 8;
  const uint32_t a_lk   = ((lane >> 4) & 1) * 8;
  const uint32_t b_lrow = (lane & 7) + ((lane >> 4) & 1) * 8;
  const uint32_t b_lk   = ((lane >> 3) & 1) * 8;

  float acc[2][8][4];
#pragma unroll
  for (int mt = 0; mt < 2; mt++)
#pragma unroll
    for (int nt = 0; nt < 8; nt++)
#pragma unroll
      for (int j = 0; j < 4; j++) acc[mt][nt][j] = 0.f;

  // Prologue: stages 0..2
#pragma unroll
  for (int s = 0; s < NSTAGE - 1; s++) {
    const uint32_t qb = sb + s * STAGE16_B;
    const int ko = s * 32;
#pragma unroll
    for (int i = 0; i < 4; i++) CP_ASYNC16(qb + ld_dst[i], ld_src[i] + ko);
    CP_COMMIT();
  }

#pragma unroll 1
  for (int kc = 0; kc < 128; kc++) {
    CP_WAIT(NSTAGE - 2);   // chunk kc arrived
    __syncthreads();       // all warps done computing chunk kc-1; loads visible
    if (kc + NSTAGE - 1 < 128) {
      const uint32_t qb = sb + ((kc + NSTAGE - 1) & (NSTAGE - 1)) * STAGE16_B;
      const int ko = (kc + NSTAGE - 1) * 32;
#pragma unroll
      for (int i = 0; i < 4; i++) CP_ASYNC16(qb + ld_dst[i], ld_src[i] + ko);
    }
    CP_COMMIT();           // always commit: keeps group counting uniform

    const uint32_t base = sb + (kc & (NSTAGE - 1)) * STAGE16_B;
#pragma unroll
    for (int ks = 0; ks < 32; ks += 16) {
      uint32_t a4[2][4];
#pragma unroll
      for (int mt = 0; mt < 2; mt++)
        ldsm_x4(a4[mt], base + (m0 + mt * 16 + a_lrow) * 80 + (ks + a_lk) * 2);
      uint32_t b4[8][2];
#pragma unroll
      for (int nt2 = 0; nt2 < 4; nt2++) {
        uint32_t t0[4];
        ldsm_x4(t0, base + 10240 + (n0 + nt2 * 16 + b_lrow) * 80 + (ks + b_lk) * 2);
        b4[nt2 * 2][0] = t0[0]; b4[nt2 * 2][1] = t0[1];
        b4[nt2 * 2 + 1][0] = t0[2]; b4[nt2 * 2 + 1][1] = t0[3];
      }
#pragma unroll
      for (int mt = 0; mt < 2; mt++)
#pragma unroll
        for (int nt = 0; nt < 8; nt++)
          mma_f16(acc[mt][nt], a4[mt], b4[nt]);
    }
  }

#pragma unroll
  for (int mt = 0; mt < 2; mt++)
#pragma unroll
    for (int nt = 0; nt < 8; nt++) {
      int m = row0 + m0 + mt * 16 + (lane >> 2);
      int n = col0 + n0 + nt * 8 + (lane & 3) * 2;
      *(float2*)&C[(size_t)m * Ntot + n] =
          make_float2(acc[mt][nt][0], acc[mt][nt][1]);
      *(float2*)&C[(size_t)(m + 8) * Ntot + n] =
          make_float2(acc[mt][nt][2], acc[mt][nt][3]);
    }
}

// ---------------------------------------------------------------------------
// Postprocess: rope(Q), rope(K), convert(V) in ONE launch (block-range select)
// grid = 16384 + 4096 + 2048 = 22528
// ---------------------------------------------------------------------------
static __device__ __forceinline__ void rope_one(
    const float* __restrict__ x, const float* __restrict__ cs,
    const float* __restrict__ sn, __half* __restrict__ out,
    int nheads, int idx) {
  int d = idx & 63;
  int h = (idx >> 6) % nheads;
  int t = idx / (64 * nheads);
  float c1 = cs[t * 128 + d],      s1 = sn[t * 128 + d];
  float c2 = cs[t * 128 + d + 64], s2 = sn[t * 128 + d + 64];
  const float* row = x + (size_t)t * (nheads * 128) + h * 128;
  __half* orow = out + (size_t)t * (nheads * 128) + h * 128;
  float x1 = row[d], x2 = row[d + 64];
  orow[d]      = __float2half_rn(x1 * c1 - x2 * s1);
  orow[d + 64] = __float2half_rn(x2 * c2 + x1 * s2);
}

__global__ void __launch_bounds__(256) postprocess_kernel(
    const float* __restrict__ Qf, const float* __restrict__ Kf,
    const float* __restrict__ Vf, const float* __restrict__ cs,
    const float* __restrict__ sn,
    __half* __restrict__ Q16, __half* __restrict__ K16,
    __half* __restrict__ V16) {
  int b = blockIdx.x;
  if (b < 16384) {
    rope_one(Qf, cs, sn, Q16, NH, b * 256 + threadIdx.x);
  } else if (b < 20480) {
    rope_one(Kf, cs, sn, K16, NKV, (b - 16384) * 256 + threadIdx.x);
  } else {
    size_t i4 = ((size_t)(b - 20480) * 256 + threadIdx.x) * 4;
    float4 v = *(const float4*)&Vf[i4];
    uint2 s;
    s.x = pkhf(v.x, v.y); s.y = pkhf(v.z, v.w);
    *(uint2*)&V16[i4] = s;
  }
}

// ---------------------------------------------------------------------------
// Flash attention, all-fp16 mma, double-buffered cp.async K/V tiles.
// BM=64 q-rows, BN=64 keys, HD=128. 4 warps; warp w owns q-rows [16w,16w+16).
// ---------------------------------------------------------------------------
#define FP 136
#define KOFF (64 * FP * 2)          // 17408: Q tile bytes
#define KVSTAGE (2 * 64 * FP * 2)   // 34816: K+V per stage
#define FLASH_SMEM (KOFF + 2 * KVSTAGE)  // 87040

__global__ void __launch_bounds__(128) flash_mma_kernel(
    const __half* __restrict__ Q16, const __half* __restrict__ K16,
    const __half* __restrict__ V16, float* __restrict__ O) {
  extern __shared__ __align__(1024) char smem[];
  __half* Qs = (__half*)smem;
  const uint32_t sbase = smem_u32(smem);

  const int h = blockIdx.y, kvh = h >> 2;
  const int qt = blockIdx.x, qbase = qt * 64;
  const int tid = threadIdx.x, w = tid >> 5, lane = tid & 31;
  const float scale = 0.08838834764831845f;

  // Q tile -> smem
#pragma unroll
  for (int i = 0; i < 8; i++) {
    int idx = i * 128 + tid;
    int r = idx >> 4, c = idx & 15;
    *(float4*)&Qs[r * FP + c * 8] =
        *(const float4*)&Q16[(size_t)(qbase + r) * (NH * HD) + h * HD + c * 8];
  }
  // Prologue: K/V tile 0 -> stage 0 via cp.async
#pragma unroll
  for (int i = 0; i < 8; i++) {
    int idx = i * 128 + tid;
    int r = idx >> 4, c = idx & 15;
    size_t g = (size_t)r * (NKV * HD) + kvh * HD + c * 8;
    CP_ASYNC16(sbase + KOFF + r * 272 + c * 16, &K16[g]);
    CP_ASYNC16(sbase + KOFF + 17408 + r * 272 + c * 16, &V16[g]);
  }
  CP_COMMIT();
  __syncthreads();

  const uint32_t a_lrow = (lane & 7) + ((lane >> 3) & 1) * 8;
  const uint32_t a_lk   = ((lane >> 4) & 1) * 8;
  const uint32_t b_lrow = (lane & 7) + ((lane >> 4) & 1) * 8;
  const uint32_t b_lk   = ((lane >> 3) & 1) * 8;
  uint32_t qa[8][4];
#pragma unroll
  for (int ks = 0; ks < 8; ks++)
    ldsm_x4(qa[ks], sbase + ((w * 16 + a_lrow) * FP + ks * 16 + a_lk) * 2);

  const int row0 = qbase + w * 16 + (lane >> 2);
  const int row1 = row0 + 8;

  float m_i[2] = {-1e30f, -1e30f}, l_i[2] = {0.f, 0.f};
  float o[16][4];
#pragma unroll
  for (int nt = 0; nt < 16; nt++)
#pragma unroll
    for (int j = 0; j < 4; j++) o[nt][j] = 0.f;

#pragma unroll 1
  for (int kt = 0; kt <= qt; kt++) {
    const int kbase = kt * 64;
    __syncthreads();   // all warps done with buffer (kt-1)&1 -> safe to refill
    if (kt < qt) {
      const int nb = (kt + 1) * 64;
      const uint32_t st = sbase + KOFF + ((kt + 1) & 1) * KVSTAGE;
#pragma unroll
      for (int i = 0; i < 8; i++) {
        int idx = i * 128 + tid;
        int r = idx >> 4, c = idx & 15;
        size_t g = (size_t)(nb + r) * (NKV * HD) + kvh * HD + c * 8;
        CP_ASYNC16(st + r * 272 + c * 16, &K16[g]);
        CP_ASYNC16(st + 17408 + r * 272 + c * 16, &V16[g]);
      }
    }
    CP_COMMIT();       // uniform group counting
    CP_WAIT(1);        // tile kt resident
    __syncthreads();

    const uint32_t ksb = sbase + KOFF + (kt & 1) * KVSTAGE;
    const uint32_t vsb = ksb + 17408;

    float s[8][4];
#pragma unroll
    for (int nt = 0; nt < 8; nt++)
#pragma unroll
      for (int j = 0; j < 4; j++) s[nt][j] = 0.f;
#pragma unroll
    for (int np = 0; np < 4; np++) {
#pragma unroll
      for (int ks = 0; ks < 8; ks++) {
        uint32_t kb[4];
        ldsm_x4(kb, ksb + ((np * 16 + b_lrow) * FP + ks * 16 + b_lk) * 2);
        mma_f16(s[np * 2],     qa[ks], kb);
        mma_f16(s[np * 2 + 1], qa[ks], kb + 2);
      }
    }

    float rm0 = -1e30f, rm1 = -1e30f;
    const bool diag = (kt == qt);
#pragma unroll
    for (int nt = 0; nt < 8; nt++) {
      int c0 = kbase + nt * 8 + (lane & 3) * 2;
#pragma unroll
      for (int j = 0; j < 4; j++) s[nt][j] *= scale;
      if (diag) {
        if (c0     > row0) s[nt][0] = -1e30f;
        if (c0 + 1 > row0) s[nt][1] = -1e30f;
        if (c0     > row1) s[nt][2] = -1e30f;
        if (c0 + 1 > row1) s[nt][3] = -1e30f;
      }
      rm0 = fmaxf(rm0, fmaxf(s[nt][0], s[nt][1]));
      rm1 = fmaxf(rm1, fmaxf(s[nt][2], s[nt][3]));
    }
#pragma unroll
    for (int off = 1; off <= 2; off <<= 1) {
      rm0 = fmaxf(rm0, __shfl_xor_sync(0xffffffffu, rm0, off));
      rm1 = fmaxf(rm1, __shfl_xor_sync(0xffffffffu, rm1, off));
    }
    float mn0 = fmaxf(m_i[0], rm0), mn1 = fmaxf(m_i[1], rm1);
    float cor0 = __expf(m_i[0] - mn0), cor1 = __expf(m_i[1] - mn1);
    float rs0 = 0.f, rs1 = 0.f;
#pragma unroll
    for (int nt = 0; nt < 8; nt++) {
      s[nt][0] = __expf(s[nt][0] - mn0); rs0 += s[nt][0];
      s[nt][1] = __expf(s[nt][1] - mn0); rs0 += s[nt][1];
      s[nt][2] = __expf(s[nt][2] - mn1); rs1 += s[nt][2];
      s[nt][3] = __expf(s[nt][3] - mn1); rs1 += s[nt][3];
    }
#pragma unroll
    for (int off = 1; off <= 2; off <<= 1) {
      rs0 += __shfl_xor_sync(0xffffffffu, rs0, off);
      rs1 += __shfl_xor_sync(0xffffffffu, rs1, off);
    }
    l_i[0] = l_i[0] * cor0 + rs0; m_i[0] = mn0;
    l_i[1] = l_i[1] * cor1 + rs1; m_i[1] = mn1;
#pragma unroll
    for (int nt = 0; nt < 16; nt++) {
      o[nt][0] *= cor0; o[nt][1] *= cor0;
      o[nt][2] *= cor1; o[nt][3] *= cor1;
    }

    // PV: single-pass fp16
#pragma unroll
    for (int kk = 0; kk < 4; kk++) {
      float* p0 = s[kk * 2];
      float* p1 = s[kk * 2 + 1];
      uint32_t ph[4];
      ph[0] = pkhf(p0[0], p0[1]); ph[1] = pkhf(p0[2], p0[3]);
      ph[2] = pkhf(p1[0], p1[1]); ph[3] = pkhf(p1[2], p1[3]);

      uint32_t vro = ((kk * 16 + (lane & 15)) * FP + ((lane >> 4) << 3)) * 2;
#pragma unroll
      for (int ntp = 0; ntp < 8; ntp++) {
        uint32_t v4[4];
        ldsm_x4_t(v4, vsb + vro + ntp * 32);
        mma_f16(o[ntp * 2],     ph, v4);
        mma_f16(o[ntp * 2 + 1], ph, v4 + 2);
      }
    }
  }

  float rl0 = 1.0f / l_i[0], rl1 = 1.0f / l_i[1];
#pragma unroll
  for (int nt = 0; nt < 16; nt++) {
    int col = h * HD + nt * 8 + (lane & 3) * 2;
    *(float2*)&O[(size_t)row0 * (NH * HD) + col] =
        make_float2(o[nt][0] * rl0, o[nt][1] * rl0);
    *(float2*)&O[(size_t)row1 * (NH * HD) + col] =
        make_float2(o[nt][2] * rl1, o[nt][3] * rl1);
  }
}

// ---------------------------------------------------------------------------
// Host launcher
// ---------------------------------------------------------------------------
extern "C" void kernel_launch(void* const* d_in, const int* in_sizes, int n_in,
                              void* d_out, int out_size) {
  const float* hidden = (const float*)d_in[0];
  const float* Wq = (const float*)d_in[1];
  const float* Wk = (const float*)d_in[2];
  const float* Wv = (const float*)d_in[3];
  const float* Wo = (const float*)d_in[4];
  const float* cosp = (const float*)d_in[5];
  const float* sinp = (const float*)d_in[6];
  const int* qcol = (const int*)d_in[8];
  const int* qrow = (const int*)d_in[9];
  const int* kcol = (const int*)d_in[10];
  const int* krow = (const int*)d_in[11];
  const int* vcol = (const int*)d_in[12];
  const int* vrow = (const int*)d_in[13];
  const int* ocol = (const int*)d_in[14];
  const int* orow = (const int*)d_in[15];

  __half *hq16, *hk16, *hv16, *wq16, *wk16, *wv16, *wo16, *ao16;
  __half *Q16, *K16, *V16;
  float *Qb, *Kb, *Vb, *Ab;
  cudaGetSymbolAddress((void**)&hq16, g_hq16);
  cudaGetSymbolAddress((void**)&hk16, g_hk16);
  cudaGetSymbolAddress((void**)&hv16, g_hv16);
  cudaGetSymbolAddress((void**)&wq16, g_wq16);
  cudaGetSymbolAddress((void**)&wk16, g_wk16);
  cudaGetSymbolAddress((void**)&wv16, g_wv16);
  cudaGetSymbolAddress((void**)&wo16, g_wo16);
  cudaGetSymbolAddress((void**)&ao16, g_ao16);
  cudaGetSymbolAddress((void**)&Qb, g_Q);
  cudaGetSymbolAddress((void**)&Kb, g_K);
  cudaGetSymbolAddress((void**)&Vb, g_V);
  cudaGetSymbolAddress((void**)&Ab, g_A);
  cudaGetSymbolAddress((void**)&Q16, g_Q16);
  cudaGetSymbolAddress((void**)&K16, g_K16);
  cudaGetSymbolAddress((void**)&V16, g_V16);

  cudaFuncSetAttribute(gemm16_mma_kernel,
                       cudaFuncAttributeMaxDynamicSharedMemorySize, GEMM16_SMEM);
  cudaFuncSetAttribute(flash_mma_kernel,
                       cudaFuncAttributeMaxDynamicSharedMemorySize, FLASH_SMEM);

  // Fused QKV gather + fp16 convert (one pass over hidden)
  gather3_convert_kernel<<<SEQ, 256>>>(hidden, qcol, kcol, vcol,
                                       hq16, hk16, hv16);

  // All weight converts in one launch
  wconvert_all_kernel<<<dim3(4, 10240), 256>>>(
      Wq, Wk, Wv, Wo, qrow, krow, vrow, orow, wq16, wk16, wv16, wo16);

  // Q projection (single-pass fp16)
  gemm16_mma_kernel<<<dim3(16, 32, 1), 256, GEMM16_SMEM>>>(
      hq16, wq16, Qb, 4096, hq16, wq16, Qb);
  // K and V projections fused via gridDim.z (single-pass fp16)
  gemm16_mma_kernel<<<dim3(16, 8, 2), 256, GEMM16_SMEM>>>(
      hk16, wk16, Kb, 1024, hv16, wv16, Vb);

  // rope(Q) + rope(K) + convert(V) in one launch
  postprocess_kernel<<<22528, 256>>>(Qb, Kb, Vb, cosp, sinp, Q16, K16, V16);

  flash_mma_kernel<<<dim3(SEQ / 64, NH), 128, FLASH_SMEM>>>(Q16, K16, V16, Ab);

  // O path: gather+fp16, single-pass fp16 GEMM
  gather1_convert_kernel<<<SEQ, 256>>>(Ab, ocol, ao16);
  gemm16_mma_kernel<<<dim3(16, 32, 1), 256, GEMM16_SMEM>>>(
      ao16, wo16, (float*)d_out, 4096, ao16, wo16, (float*)d_out);
}

// round 15
// speedup vs baseline: 1.3370x; 1.3370x over previous
#include <cuda_runtime.h>
#include <cuda_bf16.h>
#include <cuda_fp16.h>
#include <cstdint>

#define SEQ   2048
#define HDIM  4096
#define NH    32
#define NKV   8
#define HD    128

// ---------------------------------------------------------------------------
// Scratch (__device__ globals; no cudaMalloc allowed)
// ---------------------------------------------------------------------------
__device__ __half g_hq16[SEQ * HDIM], g_hk16[SEQ * HDIM], g_hv16[SEQ * HDIM];
__device__ __half g_wq16[4096 * 4096], g_wk16[1024 * 4096], g_wv16[1024 * 4096];
__device__ __half g_wo16[4096 * 4096];
__device__ __half g_ao16[SEQ * HDIM];
__device__ float g_Q[SEQ * NH * HD];
__device__ float g_K[SEQ * NKV * HD];
__device__ float g_V[SEQ * NKV * HD];
__device__ float g_A[SEQ * NH * HD];
__device__ __half g_Q16[SEQ * NH * HD];
__device__ __half g_K16[SEQ * NKV * HD];
__device__ __half g_V16[SEQ * NKV * HD];

// ---------------------------------------------------------------------------
// PTX helpers (baseline PTX only; works on plain sm_103 target)
// ---------------------------------------------------------------------------
static __device__ __forceinline__ uint32_t smem_u32(const void* p) {
  uint32_t a;
  asm("{ .reg .u64 t; cvta.to.shared.u64 t, %1; cvt.u32.u64 %0, t; }"
      : "=r"(a) : "l"(p));
  return a;
}

#define CP_ASYNC16(dst, src) \
  asm volatile("cp.async.cg.shared.global [%0], [%1], 16;" :: "r"(dst), "l"(src))
#define CP_COMMIT()   asm volatile("cp.async.commit_group;" ::: "memory")
#define CP_WAIT(n)    asm volatile("cp.async.wait_group %0;" :: "n"(n) : "memory")

static __device__ __forceinline__ void ldsm_x4(uint32_t* r, uint32_t addr) {
  asm volatile("ldmatrix.sync.aligned.m8n8.x4.shared.b16 {%0,%1,%2,%3}, [%4];"
               : "=r"(r[0]), "=r"(r[1]), "=r"(r[2]), "=r"(r[3]) : "r"(addr));
}
static __device__ __forceinline__ void ldsm_x4_t(uint32_t* r, uint32_t addr) {
  asm volatile("ldmatrix.sync.aligned.m8n8.x4.trans.shared.b16 {%0,%1,%2,%3}, [%4];"
               : "=r"(r[0]), "=r"(r[1]), "=r"(r[2]), "=r"(r[3]) : "r"(addr));
}

static __device__ __forceinline__ void mma_f16(float* d, const uint32_t* a,
                                               const uint32_t* b) {
  asm volatile(
      "mma.sync.aligned.m16n8k16.row.col.f32.f16.f16.f32 "
      "{%0,%1,%2,%3}, {%4,%5,%6,%7}, {%8,%9}, {%0,%1,%2,%3};"
      : "+f"(d[0]), "+f"(d[1]), "+f"(d[2]), "+f"(d[3])
      : "r"(a[0]), "r"(a[1]), "r"(a[2]), "r"(a[3]), "r"(b[0]), "r"(b[1]));
}

static __device__ __forceinline__ uint32_t pkhf(float a, float b) {
  __half2 t = __floats2half2_rn(a, b);
  return *(uint32_t*)&t;
}

// ---------------------------------------------------------------------------
// Fused 3-way gather + fp16 convert (QKV path): per-row smem staging.
// ---------------------------------------------------------------------------
__global__ void __launch_bounds__(256) gather3_convert_kernel(
    const float* __restrict__ in,
    const int* __restrict__ qi, const int* __restrict__ ki,
    const int* __restrict__ vi,
    __half* __restrict__ q16, __half* __restrict__ k16,
    __half* __restrict__ v16) {
  __shared__ __align__(16) float row[HDIM];
  const int t = blockIdx.x;
  const float* src = in + (size_t)t * HDIM;
#pragma unroll
  for (int i = 0; i < 4; i++) {
    int e = (i * 256 + threadIdx.x) * 4;
    *(float4*)&row[e] = *(const float4*)&src[e];
  }
  __syncthreads();
  const size_t base = (size_t)t * HDIM;
#pragma unroll
  for (int i = 0; i < 16; i++) {
    int c = i * 256 + threadIdx.x;
    q16[base + c] = __float2half_rn(row[qi[c]]);
    k16[base + c] = __float2half_rn(row[ki[c]]);
    v16[base + c] = __float2half_rn(row[vi[c]]);
  }
}

// Single-perm fp16 variant (O path)
__global__ void __launch_bounds__(256) gather1_convert_kernel(
    const float* __restrict__ in, const int* __restrict__ idx,
    __half* __restrict__ o16) {
  __shared__ __align__(16) float row[HDIM];
  const int t = blockIdx.x;
  const float* src = in + (size_t)t * HDIM;
#pragma unroll
  for (int i = 0; i < 4; i++) {
    int e = (i * 256 + threadIdx.x) * 4;
    *(float4*)&row[e] = *(const float4*)&src[e];
  }
  __syncthreads();
  const size_t base = (size_t)t * HDIM;
#pragma unroll
  for (int i = 0; i < 16; i++) {
    int c = i * 256 + threadIdx.x;
    o16[base + c] = __float2half_rn(row[idx[c]]);
  }
}

// ---------------------------------------------------------------------------
// All four weight converts in ONE launch. grid = (4, 10240); row-range select.
// ---------------------------------------------------------------------------
__global__ void __launch_bounds__(256) wconvert_all_kernel(
    const float* __restrict__ Wq, const float* __restrict__ Wk,
    const float* __restrict__ Wv, const float* __restrict__ Wo,
    const int* __restrict__ qrow, const int* __restrict__ krow,
    const int* __restrict__ vrow, const int* __restrict__ orow,
    __half* __restrict__ oq, __half* __restrict__ ok,
    __half* __restrict__ ov, __half* __restrict__ oo) {
  int j = blockIdx.y;
  const float* W; const int* ridx; __half* out; int jj;
  if (j < 4096)      { W = Wq; ridx = qrow; out = oq; jj = j; }
  else if (j < 5120) { W = Wk; ridx = krow; out = ok; jj = j - 4096; }
  else if (j < 6144) { W = Wv; ridx = vrow; out = ov; jj = j - 5120; }
  else               { W = Wo; ridx = orow; out = oo; jj = j - 6144; }
  int c4 = (blockIdx.x * 256 + threadIdx.x) * 4;
  float4 v = *(const float4*)&W[(size_t)ridx[jj] * HDIM + c4];
  uint2 s;
  s.x = pkhf(v.x, v.y); s.y = pkhf(v.z, v.w);
  *(uint2*)&out[(size_t)jj * HDIM + c4] = s;
}

// ---------------------------------------------------------------------------
// Single-pass fp16 GEMM: C = A @ B^T, fp32 accum.  (R10 config: 2-stage,
// 40KB smem -- occupancy binds before pipeline depth on this workload.)
// BM=BN=128, BK=32, 8 warps x (32x64). blockIdx.z selects problem (K/V fuse).
// ---------------------------------------------------------------------------
#define STAGE16_B 20480
#define GEMM16_SMEM (2 * STAGE16_B)

__global__ void __launch_bounds__(256) gemm16_mma_kernel(
    const __half* A_, const __half* B_, float* C_, int Ntot,
    const __half* A2, const __half* B2, float* C2) {
  const __half* A = A_; const __half* B = B_; float* C = C_;
  if (blockIdx.z == 1) { A = A2; B = B2; C = C2; }

  extern __shared__ __align__(1024) char smem[];
  uint32_t sb = smem_u32(smem);
  const int tid = threadIdx.x, wid = tid >> 5, lane = tid & 31;
  const int row0 = blockIdx.x * 128, col0 = blockIdx.y * 128;

  const __half* ld_src[4];
  uint32_t ld_dst[4];
#pragma unroll
  for (int i = 0; i < 4; i++) {
    int t = i * 256 + tid;
    int mat = t >> 9, r = (t >> 2) & 127, c = t & 3;
    const __half* base = (mat == 0) ? A + (size_t)row0 * 4096
                                    : B + (size_t)col0 * 4096;
    ld_src[i] = base + (size_t)r * 4096 + c * 8;
    ld_dst[i] = (uint32_t)(mat * 10240 + r * 80 + c * 16);
  }

  const int m0 = (wid & 3) * 32, n0 = (wid >> 2) * 64;
  const uint32_t a_lrow = (lane & 7) + ((lane >> 3) & 1) * 8;
  const uint32_t a_lk   = ((lane >> 4) & 1) * 8;
  const uint32_t b_lrow = (lane & 7) + ((lane >> 4) & 1) * 8;
  const uint32_t b_lk   = ((lane >> 3) & 1) * 8;

  float acc[2][8][4];
#pragma unroll
  for (int mt = 0; mt < 2; mt++)
#pragma unroll
    for (int nt = 0; nt < 8; nt++)
#pragma unroll
      for (int j = 0; j < 4; j++) acc[mt][nt][j] = 0.f;

#pragma unroll
  for (int i = 0; i < 4; i++) CP_ASYNC16(sb + ld_dst[i], ld_src[i]);
  CP_COMMIT();

#pragma unroll 1
  for (int kc = 0; kc < 128; kc++) {
    const int p = kc & 1;
    if (kc + 1 < 128) {
      const uint32_t qb = sb + (p ^ 1) * STAGE16_B;
      const int ko = (kc + 1) * 32;
#pragma unroll
      for (int i = 0; i < 4; i++) CP_ASYNC16(qb + ld_dst[i], ld_src[i] + ko);
      CP_COMMIT();
      CP_WAIT(1);
    } else {
      CP_WAIT(0);
    }
    __syncthreads();

    const uint32_t base = sb + p * STAGE16_B;
#pragma unroll
    for (int ks = 0; ks < 32; ks += 16) {
      uint32_t a4[2][4];
#pragma unroll
      for (int mt = 0; mt < 2; mt++)
        ldsm_x4(a4[mt], base + (m0 + mt * 16 + a_lrow) * 80 + (ks + a_lk) * 2);
      uint32_t b4[8][2];
#pragma unroll
      for (int nt2 = 0; nt2 < 4; nt2++) {
        uint32_t t0[4];
        ldsm_x4(t0, base + 10240 + (n0 + nt2 * 16 + b_lrow) * 80 + (ks + b_lk) * 2);
        b4[nt2 * 2][0] = t0[0]; b4[nt2 * 2][1] = t0[1];
        b4[nt2 * 2 + 1][0] = t0[2]; b4[nt2 * 2 + 1][1] = t0[3];
      }
#pragma unroll
      for (int mt = 0; mt < 2; mt++)
#pragma unroll
        for (int nt = 0; nt < 8; nt++)
          mma_f16(acc[mt][nt], a4[mt], b4[nt]);
    }
    __syncthreads();
  }

#pragma unroll
  for (int mt = 0; mt < 2; mt++)
#pragma unroll
    for (int nt = 0; nt < 8; nt++) {
      int m = row0 + m0 + mt * 16 + (lane >> 2);
      int n = col0 + n0 + nt * 8 + (lane & 3) * 2;
      *(float2*)&C[(size_t)m * Ntot + n] =
          make_float2(acc[mt][nt][0], acc[mt][nt][1]);
      *(float2*)&C[(size_t)(m + 8) * Ntot + n] =
          make_float2(acc[mt][nt][2], acc[mt][nt][3]);
    }
}

// ---------------------------------------------------------------------------
// Postprocess: rope(Q), rope(K), convert(V) in ONE launch (block-range select)
// grid = 16384 + 4096 + 2048 = 22528
// ---------------------------------------------------------------------------
static __device__ __forceinline__ void rope_one(
    const float* __restrict__ x, const float* __restrict__ cs,
    const float* __restrict__ sn, __half* __restrict__ out,
    int nheads, int idx) {
  int d = idx & 63;
  int h = (idx >> 6) % nheads;
  int t = idx / (64 * nheads);
  float c1 = cs[t * 128 + d],      s1 = sn[t * 128 + d];
  float c2 = cs[t * 128 + d + 64], s2 = sn[t * 128 + d + 64];
  const float* row = x + (size_t)t * (nheads * 128) + h * 128;
  __half* orow = out + (size_t)t * (nheads * 128) + h * 128;
  float x1 = row[d], x2 = row[d + 64];
  orow[d]      = __float2half_rn(x1 * c1 - x2 * s1);
  orow[d + 64] = __float2half_rn(x2 * c2 + x1 * s2);
}

__global__ void __launch_bounds__(256) postprocess_kernel(
    const float* __restrict__ Qf, const float* __restrict__ Kf,
    const float* __restrict__ Vf, const float* __restrict__ cs,
    const float* __restrict__ sn,
    __half* __restrict__ Q16, __half* __restrict__ K16,
    __half* __restrict__ V16) {
  int b = blockIdx.x;
  if (b < 16384) {
    rope_one(Qf, cs, sn, Q16, NH, b * 256 + threadIdx.x);
  } else if (b < 20480) {
    rope_one(Kf, cs, sn, K16, NKV, (b - 16384) * 256 + threadIdx.x);
  } else {
    size_t i4 = ((size_t)(b - 20480) * 256 + threadIdx.x) * 4;
    float4 v = *(const float4*)&Vf[i4];
    uint2 s;
    s.x = pkhf(v.x, v.y); s.y = pkhf(v.z, v.w);
    *(uint2*)&V16[i4] = s;
  }
}

// ---------------------------------------------------------------------------
// Flash attention, all-fp16 mma (R10 config: synchronous K/V tile loads,
// 52KB smem -> 4 CTAs/SM; occupancy beats cp.async overlap here).
// BM=64 q-rows, BN=64 keys, HD=128. 4 warps; warp w owns q-rows [16w,16w+16).
// ---------------------------------------------------------------------------
#define FP 136
#define FLASH_SMEM (3 * 64 * FP * 2)

__global__ void __launch_bounds__(128) flash_mma_kernel(
    const __half* __restrict__ Q16, const __half* __restrict__ K16,
    const __half* __restrict__ V16, float* __restrict__ O) {
  extern __shared__ __align__(1024) char smem[];
  __half* Qs = (__half*)smem;
  __half* Ks = Qs + 64 * FP;
  __half* Vs = Qs + 2 * 64 * FP;

  const int h = blockIdx.y, kvh = h >> 2;
  const int qt = blockIdx.x, qbase = qt * 64;
  const int tid = threadIdx.x, w = tid >> 5, lane = tid & 31;
  const float scale = 0.08838834764831845f;

#pragma unroll
  for (int i = 0; i < 8; i++) {
    int idx = i * 128 + tid;
    int r = idx >> 4, c = idx & 15;
    *(float4*)&Qs[r * FP + c * 8] =
        *(const float4*)&Q16[(size_t)(qbase + r) * (NH * HD) + h * HD + c * 8];
  }
  __syncthreads();

  const uint32_t a_lrow = (lane & 7) + ((lane >> 3) & 1) * 8;
  const uint32_t a_lk   = ((lane >> 4) & 1) * 8;
  const uint32_t b_lrow = (lane & 7) + ((lane >> 4) & 1) * 8;
  const uint32_t b_lk   = ((lane >> 3) & 1) * 8;
  uint32_t qa[8][4];
  {
    uint32_t qsb = smem_u32(Qs);
#pragma unroll
    for (int ks = 0; ks < 8; ks++)
      ldsm_x4(qa[ks], qsb + ((w * 16 + a_lrow) * FP + ks * 16 + a_lk) * 2);
  }

  const int row0 = qbase + w * 16 + (lane >> 2);
  const int row1 = row0 + 8;

  float m_i[2] = {-1e30f, -1e30f}, l_i[2] = {0.f, 0.f};
  float o[16][4];
#pragma unroll
  for (int nt = 0; nt < 16; nt++)
#pragma unroll
    for (int j = 0; j < 4; j++) o[nt][j] = 0.f;

  const uint32_t ksb = smem_u32(Ks), vsb = smem_u32(Vs);

#pragma unroll 1
  for (int kt = 0; kt <= qt; kt++) {
    const int kbase = kt * 64;
    __syncthreads();
#pragma unroll
    for (int i = 0; i < 8; i++) {
      int idx = i * 128 + tid;
      int r = idx >> 4, c = idx & 15;
      size_t g = (size_t)(kbase + r) * (NKV * HD) + kvh * HD + c * 8;
      *(float4*)&Ks[r * FP + c * 8] = *(const float4*)&K16[g];
      *(float4*)&Vs[r * FP + c * 8] = *(const float4*)&V16[g];
    }
    __syncthreads();

    float s[8][4];
#pragma unroll
    for (int nt = 0; nt < 8; nt++)
#pragma unroll
      for (int j = 0; j < 4; j++) s[nt][j] = 0.f;
#pragma unroll
    for (int np = 0; np < 4; np++) {
#pragma unroll
      for (int ks = 0; ks < 8; ks++) {
        uint32_t kb[4];
        ldsm_x4(kb, ksb + ((np * 16 + b_lrow) * FP + ks * 16 + b_lk) * 2);
        mma_f16(s[np * 2],     qa[ks], kb);
        mma_f16(s[np * 2 + 1], qa[ks], kb + 2);
      }
    }

    float rm0 = -1e30f, rm1 = -1e30f;
    const bool diag = (kt == qt);
#pragma unroll
    for (int nt = 0; nt < 8; nt++) {
      int c0 = kbase + nt * 8 + (lane & 3) * 2;
#pragma unroll
      for (int j = 0; j < 4; j++) s[nt][j] *= scale;
      if (diag) {
        if (c0     > row0) s[nt][0] = -1e30f;
        if (c0 + 1 > row0) s[nt][1] = -1e30f;
        if (c0     > row1) s[nt][2] = -1e30f;
        if (c0 + 1 > row1) s[nt][3] = -1e30f;
      }
      rm0 = fmaxf(rm0, fmaxf(s[nt][0], s[nt][1]));
      rm1 = fmaxf(rm1, fmaxf(s[nt][2], s[nt][3]));
    }
#pragma unroll
    for (int off = 1; off <= 2; off <<= 1) {
      rm0 = fmaxf(rm0, __shfl_xor_sync(0xffffffffu, rm0, off));
      rm1 = fmaxf(rm1, __shfl_xor_sync(0xffffffffu, rm1, off));
    }
    float mn0 = fmaxf(m_i[0], rm0), mn1 = fmaxf(m_i[1], rm1);
    float cor0 = __expf(m_i[0] - mn0), cor1 = __expf(m_i[1] - mn1);
    float rs0 = 0.f, rs1 = 0.f;
#pragma unroll
    for (int nt = 0; nt < 8; nt++) {
      s[nt][0] = __expf(s[nt][0] - mn0); rs0 += s[nt][0];
      s[nt][1] = __expf(s[nt][1] - mn0); rs0 += s[nt][1];
      s[nt][2] = __expf(s[nt][2] - mn1); rs1 += s[nt][2];
      s[nt][3] = __expf(s[nt][3] - mn1); rs1 += s[nt][3];
    }
#pragma unroll
    for (int off = 1; off <= 2; off <<= 1) {
      rs0 += __shfl_xor_sync(0xffffffffu, rs0, off);
      rs1 += __shfl_xor_sync(0xffffffffu, rs1, off);
    }
    l_i[0] = l_i[0] * cor0 + rs0; m_i[0] = mn0;
    l_i[1] = l_i[1] * cor1 + rs1; m_i[1] = mn1;
#pragma unroll
    for (int nt = 0; nt < 16; nt++) {
      o[nt][0] *= cor0; o[nt][1] *= cor0;
      o[nt][2] *= cor1; o[nt][3] *= cor1;
    }

    // PV: single-pass fp16
#pragma unroll
    for (int kk = 0; kk < 4; kk++) {
      float* p0 = s[kk * 2];
      float* p1 = s[kk * 2 + 1];
      uint32_t ph[4];
      ph[0] = pkhf(p0[0], p0[1]); ph[1] = pkhf(p0[2], p0[3]);
      ph[2] = pkhf(p1[0], p1[1]); ph[3] = pkhf(p1[2], p1[3]);

      uint32_t vro = ((kk * 16 + (lane & 15)) * FP + ((lane >> 4) << 3)) * 2;
#pragma unroll
      for (int ntp = 0; ntp < 8; ntp++) {
        uint32_t v4[4];
        ldsm_x4_t(v4, vsb + vro + ntp * 32);
        mma_f16(o[ntp * 2],     ph, v4);
        mma_f16(o[ntp * 2 + 1], ph, v4 + 2);
      }
    }
  }

  float rl0 = 1.0f / l_i[0], rl1 = 1.0f / l_i[1];
#pragma unroll
  for (int nt = 0; nt < 16; nt++) {
    int col = h * HD + nt * 8 + (lane & 3) * 2;
    *(float2*)&O[(size_t)row0 * (NH * HD) + col] =
        make_float2(o[nt][0] * rl0, o[nt][1] * rl0);
    *(float2*)&O[(size_t)row1 * (NH * HD) + col] =
        make_float2(o[nt][2] * rl1, o[nt][3] * rl1);
  }
}

// ---------------------------------------------------------------------------
// Host launcher
// ---------------------------------------------------------------------------
extern "C" void kernel_launch(void* const* d_in, const int* in_sizes, int n_in,
                              void* d_out, int out_size) {
  const float* hidden = (const float*)d_in[0];
  const float* Wq = (const float*)d_in[1];
  const float* Wk = (const float*)d_in[2];
  const float* Wv = (const float*)d_in[3];
  const float* Wo = (const float*)d_in[4];
  const float* cosp = (const float*)d_in[5];
  const float* sinp = (const float*)d_in[6];
  const int* qcol = (const int*)d_in[8];
  const int* qrow = (const int*)d_in[9];
  const int* kcol = (const int*)d_in[10];
  const int* krow = (const int*)d_in[11];
  const int* vcol = (const int*)d_in[12];
  const int* vrow = (const int*)d_in[13];
  const int* ocol = (const int*)d_in[14];
  const int* orow = (const int*)d_in[15];

  __half *hq16, *hk16, *hv16, *wq16, *wk16, *wv16, *wo16, *ao16;
  __half *Q16, *K16, *V16;
  float *Qb, *Kb, *Vb, *Ab;
  cudaGetSymbolAddress((void**)&hq16, g_hq16);
  cudaGetSymbolAddress((void**)&hk16, g_hk16);
  cudaGetSymbolAddress((void**)&hv16, g_hv16);
  cudaGetSymbolAddress((void**)&wq16, g_wq16);
  cudaGetSymbolAddress((void**)&wk16, g_wk16);
  cudaGetSymbolAddress((void**)&wv16, g_wv16);
  cudaGetSymbolAddress((void**)&wo16, g_wo16);
  cudaGetSymbolAddress((void**)&ao16, g_ao16);
  cudaGetSymbolAddress((void**)&Qb, g_Q);
  cudaGetSymbolAddress((void**)&Kb, g_K);
  cudaGetSymbolAddress((void**)&Vb, g_V);
  cudaGetSymbolAddress((void**)&Ab, g_A);
  cudaGetSymbolAddress((void**)&Q16, g_Q16);
  cudaGetSymbolAddress((void**)&K16, g_K16);
  cudaGetSymbolAddress((void**)&V16, g_V16);

  cudaFuncSetAttribute(gemm16_mma_kernel,
                       cudaFuncAttributeMaxDynamicSharedMemorySize, GEMM16_SMEM);
  cudaFuncSetAttribute(flash_mma_kernel,
                       cudaFuncAttributeMaxDynamicSharedMemorySize, FLASH_SMEM);

  // Fused QKV gather + fp16 convert (one pass over hidden)
  gather3_convert_kernel<<<SEQ, 256>>>(hidden, qcol, kcol, vcol,
                                       hq16, hk16, hv16);

  // All weight converts in one launch
  wconvert_all_kernel<<<dim3(4, 10240), 256>>>(
      Wq, Wk, Wv, Wo, qrow, krow, vrow, orow, wq16, wk16, wv16, wo16);

  // Q projection (single-pass fp16)
  gemm16_mma_kernel<<<dim3(16, 32, 1), 256, GEMM16_SMEM>>>(
      hq16, wq16, Qb, 4096, hq16, wq16, Qb);
  // K and V projections fused via gridDim.z (single-pass fp16)
  gemm16_mma_kernel<<<dim3(16, 8, 2), 256, GEMM16_SMEM>>>(
      hk16, wk16, Kb, 1024, hv16, wv16, Vb);

  // rope(Q) + rope(K) + convert(V) in one launch
  postprocess_kernel<<<22528, 256>>>(Qb, Kb, Vb, cosp, sinp, Q16, K16, V16);

  flash_mma_kernel<<<dim3(SEQ / 64, NH), 128, FLASH_SMEM>>>(Q16, K16, V16, Ab);

  // O path: gather+fp16, single-pass fp16 GEMM
  gather1_convert_kernel<<<SEQ, 256>>>(Ab, ocol, ao16);
  gemm16_mma_kernel<<<dim3(16, 32, 1), 256, GEMM16_SMEM>>>(
      ao16, wo16, (float*)d_out, 4096, ao16, wo16, (float*)d_out);
}

// round 17
// speedup vs baseline: 1.4027x; 1.0492x over previous
#include <cuda_runtime.h>
#include <cuda_bf16.h>
#include <cuda_fp16.h>
#include <cstdint>

#define SEQ   2048
#define HDIM  4096
#define NH    32
#define NKV   8
#define HD    128

// ---------------------------------------------------------------------------
// Scratch (__device__ globals; no cudaMalloc allowed)
// ---------------------------------------------------------------------------
__device__ __half g_hq16[SEQ * HDIM], g_hk16[SEQ * HDIM], g_hv16[SEQ * HDIM];
__device__ __half g_wq16[4096 * 4096], g_wk16[1024 * 4096], g_wv16[1024 * 4096];
__device__ __half g_wo16[4096 * 4096];
__device__ __half g_ao16[SEQ * HDIM];
__device__ float g_A[SEQ * NH * HD];
__device__ __half g_Q16[SEQ * NH * HD];
__device__ __half g_K16[SEQ * NKV * HD];
__device__ __half g_V16[SEQ * NKV * HD];

// ---------------------------------------------------------------------------
// PTX helpers (baseline PTX only; works on plain sm_103 target)
// ---------------------------------------------------------------------------
static __device__ __forceinline__ uint32_t smem_u32(const void* p) {
  uint32_t a;
  asm("{ .reg .u64 t; cvta.to.shared.u64 t, %1; cvt.u32.u64 %0, t; }"
      : "=r"(a) : "l"(p));
  return a;
}

#define CP_ASYNC16(dst, src) \
  asm volatile("cp.async.cg.shared.global [%0], [%1], 16;" :: "r"(dst), "l"(src))
#define CP_COMMIT()   asm volatile("cp.async.commit_group;" ::: "memory")
#define CP_WAIT(n)    asm volatile("cp.async.wait_group %0;" :: "n"(n) : "memory")

static __device__ __forceinline__ void ldsm_x4(uint32_t* r, uint32_t addr) {
  asm volatile("ldmatrix.sync.aligned.m8n8.x4.shared.b16 {%0,%1,%2,%3}, [%4];"
               : "=r"(r[0]), "=r"(r[1]), "=r"(r[2]), "=r"(r[3]) : "r"(addr));
}
static __device__ __forceinline__ void ldsm_x4_t(uint32_t* r, uint32_t addr) {
  asm volatile("ldmatrix.sync.aligned.m8n8.x4.trans.shared.b16 {%0,%1,%2,%3}, [%4];"
               : "=r"(r[0]), "=r"(r[1]), "=r"(r[2]), "=r"(r[3]) : "r"(addr));
}

static __device__ __forceinline__ void mma_f16(float* d, const uint32_t* a,
                                               const uint32_t* b) {
  asm volatile(
      "mma.sync.aligned.m16n8k16.row.col.f32.f16.f16.f32 "
      "{%0,%1,%2,%3}, {%4,%5,%6,%7}, {%8,%9}, {%0,%1,%2,%3};"
      : "+f"(d[0]), "+f"(d[1]), "+f"(d[2]), "+f"(d[3])
      : "r"(a[0]), "r"(a[1]), "r"(a[2]), "r"(a[3]), "r"(b[0]), "r"(b[1]));
}

static __device__ __forceinline__ uint32_t pkhf(float a, float b) {
  __half2 t = __floats2half2_rn(a, b);
  return *(uint32_t*)&t;
}

// ---------------------------------------------------------------------------
// Fused 3-way gather + fp16 convert (QKV path): per-row smem staging.
// ---------------------------------------------------------------------------
__global__ void __launch_bounds__(256) gather3_convert_kernel(
    const float* __restrict__ in,
    const int* __restrict__ qi, const int* __restrict__ ki,
    const int* __restrict__ vi,
    __half* __restrict__ q16, __half* __restrict__ k16,
    __half* __restrict__ v16) {
  __shared__ __align__(16) float row[HDIM];
  const int t = blockIdx.x;
  const float* src = in + (size_t)t * HDIM;
#pragma unroll
  for (int i = 0; i < 4; i++) {
    int e = (i * 256 + threadIdx.x) * 4;
    *(float4*)&row[e] = *(const float4*)&src[e];
  }
  __syncthreads();
  const size_t base = (size_t)t * HDIM;
#pragma unroll
  for (int i = 0; i < 16; i++) {
    int c = i * 256 + threadIdx.x;
    q16[base + c] = __float2half_rn(row[qi[c]]);
    k16[base + c] = __float2half_rn(row[ki[c]]);
    v16[base + c] = __float2half_rn(row[vi[c]]);
  }
}

// Single-perm fp16 variant (O path)
__global__ void __launch_bounds__(256) gather1_convert_kernel(
    const float* __restrict__ in, const int* __restrict__ idx,
    __half* __restrict__ o16) {
  __shared__ __align__(16) float row[HDIM];
  const int t = blockIdx.x;
  const float* src = in + (size_t)t * HDIM;
#pragma unroll
  for (int i = 0; i < 4; i++) {
    int e = (i * 256 + threadIdx.x) * 4;
    *(float4*)&row[e] = *(const float4*)&src[e];
  }
  __syncthreads();
  const size_t base = (size_t)t * HDIM;
#pragma unroll
  for (int i = 0; i < 16; i++) {
    int c = i * 256 + threadIdx.x;
    o16[base + c] = __float2half_rn(row[idx[c]]);
  }
}

// ---------------------------------------------------------------------------
// All four weight converts in ONE launch; one block per output row.
// grid = 10240, 256 threads, 4 float4 per thread.
// ---------------------------------------------------------------------------
__global__ void __launch_bounds__(256) wconvert_all_kernel(
    const float* __restrict__ Wq, const float* __restrict__ Wk,
    const float* __restrict__ Wv, const float* __restrict__ Wo,
    const int* __restrict__ qrow, const int* __restrict__ krow,
    const int* __restrict__ vrow, const int* __restrict__ orow,
    __half* __restrict__ oq, __half* __restrict__ ok,
    __half* __restrict__ ov, __half* __restrict__ oo) {
  int j = blockIdx.x;
  const float* W; const int* ridx; __half* out; int jj;
  if (j < 4096)      { W = Wq; ridx = qrow; out = oq; jj = j; }
  else if (j < 5120) { W = Wk; ridx = krow; out = ok; jj = j - 4096; }
  else if (j < 6144) { W = Wv; ridx = vrow; out = ov; jj = j - 5120; }
  else               { W = Wo; ridx = orow; out = oo; jj = j - 6144; }
  const float* src = &W[(size_t)ridx[jj] * HDIM];
  __half* dst = &out[(size_t)jj * HDIM];
#pragma unroll
  for (int i = 0; i < 4; i++) {
    int c4 = (i * 256 + threadIdx.x) * 4;
    float4 v = *(const float4*)&src[c4];
    uint2 s;
    s.x = pkhf(v.x, v.y); s.y = pkhf(v.z, v.w);
    *(uint2*)&dst[c4] = s;
  }
}

// ---------------------------------------------------------------------------
// Fused QKV GEMM, single launch (768 linear CTAs):
//   bid [0,512)   : Q tiles (rope epilogue -> Q16)
//   bid [512,640) : K tiles (rope epilogue -> K16)
//   bid [640,768) : V tiles (convert epilogue -> V16)
// Mainloop = R10 config (2-stage, 40KB). N-tile (128) == one head, so the
// rope pair (d, d^64) is CTA-local: exchange via 32KB smem slice per mt.
// Rope math applied to the SAME fp32 accumulators postprocess used to read
// from gmem -> bit-identical results.
// ---------------------------------------------------------------------------
#define STAGE16_B 20480
#define GEMM16_SMEM (2 * STAGE16_B)

__global__ void __launch_bounds__(256) gemm16_qkv_kernel(
    const __half* __restrict__ hq, const __half* __restrict__ hk,
    const __half* __restrict__ hv,
    const __half* __restrict__ wq, const __half* __restrict__ wk,
    const __half* __restrict__ wv,
    const float* __restrict__ cosp, const float* __restrict__ sinp,
    __half* __restrict__ Q16, __half* __restrict__ K16,
    __half* __restrict__ V16) {
  const int bid = blockIdx.x;
  const __half* A; const __half* B; __half* out16;
  int Ntot, mtile, ntile, do_rope;
  if (bid < 512) {
    A = hq; B = wq; out16 = Q16; Ntot = 4096;
    mtile = bid & 15; ntile = bid >> 4; do_rope = 1;
  } else if (bid < 640) {
    int i = bid - 512;
    A = hk; B = wk; out16 = K16; Ntot = 1024;
    mtile = i & 15; ntile = i >> 4; do_rope = 1;
  } else {
    int i = bid - 640;
    A = hv; B = wv; out16 = V16; Ntot = 1024;
    mtile = i & 15; ntile = i >> 4; do_rope = 0;
  }

  extern __shared__ __align__(1024) char smem[];
  uint32_t sb = smem_u32(smem);
  const int tid = threadIdx.x, wid = tid >> 5, lane = tid & 31;
  const int row0 = mtile * 128, col0 = ntile * 128;

  const __half* ld_src[4];
  uint32_t ld_dst[4];
#pragma unroll
  for (int i = 0; i < 4; i++) {
    int t = i * 256 + tid;
    int mat = t >> 9, r = (t >> 2) & 127, c = t & 3;
    const __half* base = (mat == 0) ? A + (size_t)row0 * 4096
                                    : B + (size_t)col0 * 4096;
    ld_src[i] = base + (size_t)r * 4096 + c * 8;
    ld_dst[i] = (uint32_t)(mat * 10240 + r * 80 + c * 16);
  }

  const int m0 = (wid & 3) * 32, n0 = (wid >> 2) * 64;
  const uint32_t a_lrow = (lane & 7) + ((lane >> 3) & 1) * 8;
  const uint32_t a_lk   = ((lane >> 4) & 1) * 8;
  const uint32_t b_lrow = (lane & 7) + ((lane >> 4) & 1) * 8;
  const uint32_t b_lk   = ((lane >> 3) & 1) * 8;

  float acc[2][8][4];
#pragma unroll
  for (int mt = 0; mt < 2; mt++)
#pragma unroll
    for (int nt = 0; nt < 8; nt++)
#pragma unroll
      for (int j = 0; j < 4; j++) acc[mt][nt][j] = 0.f;

#pragma unroll
  for (int i = 0; i < 4; i++) CP_ASYNC16(sb + ld_dst[i], ld_src[i]);
  CP_COMMIT();

#pragma unroll 1
  for (int kc = 0; kc < 128; kc++) {
    const int p = kc & 1;
    if (kc + 1 < 128) {
      const uint32_t qb = sb + (p ^ 1) * STAGE16_B;
      const int ko = (kc + 1) * 32;
#pragma unroll
      for (int i = 0; i < 4; i++) CP_ASYNC16(qb + ld_dst[i], ld_src[i] + ko);
      CP_COMMIT();
      CP_WAIT(1);
    } else {
      CP_WAIT(0);
    }
    __syncthreads();

    const uint32_t base = sb + p * STAGE16_B;
#pragma unroll
    for (int ks = 0; ks < 32; ks += 16) {
      uint32_t a4[2][4];
#pragma unroll
      for (int mt = 0; mt < 2; mt++)
        ldsm_x4(a4[mt], base + (m0 + mt * 16 + a_lrow) * 80 + (ks + a_lk) * 2);
      uint32_t b4[8][2];
#pragma unroll
      for (int nt2 = 0; nt2 < 4; nt2++) {
        uint32_t t0[4];
        ldsm_x4(t0, base + 10240 + (n0 + nt2 * 16 + b_lrow) * 80 + (ks + b_lk) * 2);
        b4[nt2 * 2][0] = t0[0]; b4[nt2 * 2][1] = t0[1];
        b4[nt2 * 2 + 1][0] = t0[2]; b4[nt2 * 2 + 1][1] = t0[3];
      }
#pragma unroll
      for (int mt = 0; mt < 2; mt++)
#pragma unroll
        for (int nt = 0; nt < 8; nt++)
          mma_f16(acc[mt][nt], a4[mt], b4[nt]);
    }
    __syncthreads();
  }

  if (do_rope) {
    // Rope epilogue: smem exchange of the (d, d^64) partner, per mt slice.
    float* xs = (float*)smem;          // 64 rows x 128 cols fp32 = 32KB
    const int rs = (wid & 3) * 16;     // local row base of this warp's slice
    const int csh = n0;                // 0 or 64
    const int rb = lane >> 2;
    const int cb = (lane & 3) * 2;
#pragma unroll 1
    for (int mt = 0; mt < 2; mt++) {
      __syncthreads();
#pragma unroll
      for (int nt = 0; nt < 8; nt++) {
        int c = csh + nt * 8 + cb;
        xs[(rs + rb) * 128 + c]         = acc[mt][nt][0];
        xs[(rs + rb) * 128 + c + 1]     = acc[mt][nt][1];
        xs[(rs + rb + 8) * 128 + c]     = acc[mt][nt][2];
        xs[(rs + rb + 8) * 128 + c + 1] = acc[mt][nt][3];
      }
      __syncthreads();
      const int gm0 = row0 + (wid & 3) * 32 + mt * 16 + rb;
      const int gm1 = gm0 + 8;
      const int lr0 = rs + rb, lr1 = lr0 + 8;
#pragma unroll
      for (int nt = 0; nt < 8; nt++) {
        int dd = csh + nt * 8 + cb;    // col within head (tile == head)
        float sgn = (dd < 64) ? -1.f : 1.f;
        float p00 = xs[lr0 * 128 + (dd ^ 64)];
        float p01 = xs[lr0 * 128 + ((dd + 1) ^ 64)];
        float p10 = xs[lr1 * 128 + (dd ^ 64)];
        float p11 = xs[lr1 * 128 + ((dd + 1) ^ 64)];
        float c00 = cosp[gm0 * 128 + dd],     s00 = sinp[gm0 * 128 + dd];
        float c01 = cosp[gm0 * 128 + dd + 1], s01 = sinp[gm0 * 128 + dd + 1];
        float c10 = cosp[gm1 * 128 + dd],     s10 = sinp[gm1 * 128 + dd];
        float c11 = cosp[gm1 * 128 + dd + 1], s11 = sinp[gm1 * 128 + dd + 1];
        uint32_t o0 = pkhf(acc[mt][nt][0] * c00 + sgn * p00 * s00,
                           acc[mt][nt][1] * c01 + sgn * p01 * s01);
        uint32_t o1 = pkhf(acc[mt][nt][2] * c10 + sgn * p10 * s10,
                           acc[mt][nt][3] * c11 + sgn * p11 * s11);
        *(uint32_t*)&out16[(size_t)gm0 * Ntot + col0 + dd] = o0;
        *(uint32_t*)&out16[(size_t)gm1 * Ntot + col0 + dd] = o1;
      }
    }
  } else {
    // V: direct fp16 convert
#pragma unroll
    for (int mt = 0; mt < 2; mt++)
#pragma unroll
      for (int nt = 0; nt < 8; nt++) {
        int m = row0 + m0 + mt * 16 + (lane >> 2);
        int n = col0 + n0 + nt * 8 + (lane & 3) * 2;
        *(uint32_t*)&out16[(size_t)m * Ntot + n] =
            pkhf(acc[mt][nt][0], acc[mt][nt][1]);
        *(uint32_t*)&out16[(size_t)(m + 8) * Ntot + n] =
            pkhf(acc[mt][nt][2], acc[mt][nt][3]);
      }
  }
}

// ---------------------------------------------------------------------------
// O-projection GEMM (fp32 output to d_out); mainloop identical.
// ---------------------------------------------------------------------------
__global__ void __launch_bounds__(256) gemm16_mma_kernel(
    const __half* __restrict__ A, const __half* __restrict__ B,
    float* __restrict__ C, int Ntot) {
  extern __shared__ __align__(1024) char smem[];
  uint32_t sb = smem_u32(smem);
  const int tid = threadIdx.x, wid = tid >> 5, lane = tid & 31;
  const int row0 = blockIdx.x * 128, col0 = blockIdx.y * 128;

  const __half* ld_src[4];
  uint32_t ld_dst[4];
#pragma unroll
  for (int i = 0; i < 4; i++) {
    int t = i * 256 + tid;
    int mat = t >> 9, r = (t >> 2) & 127, c = t & 3;
    const __half* base = (mat == 0) ? A + (size_t)row0 * 4096
                                    : B + (size_t)col0 * 4096;
    ld_src[i] = base + (size_t)r * 4096 + c * 8;
    ld_dst[i] = (uint32_t)(mat * 10240 + r * 80 + c * 16);
  }

  const int m0 = (wid & 3) * 32, n0 = (wid >> 2) * 64;
  const uint32_t a_lrow = (lane & 7) + ((lane >> 3) & 1) * 8;
  const uint32_t a_lk   = ((lane >> 4) & 1) * 8;
  const uint32_t b_lrow = (lane & 7) + ((lane >> 4) & 1) * 8;
  const uint32_t b_lk   = ((lane >> 3) & 1) * 8;

  float acc[2][8][4];
#pragma unroll
  for (int mt = 0; mt < 2; mt++)
#pragma unroll
    for (int nt = 0; nt < 8; nt++)
#pragma unroll
      for (int j = 0; j < 4; j++) acc[mt][nt][j] = 0.f;

#pragma unroll
  for (int i = 0; i < 4; i++) CP_ASYNC16(sb + ld_dst[i], ld_src[i]);
  CP_COMMIT();

#pragma unroll 1
  for (int kc = 0; kc < 128; kc++) {
    const int p = kc & 1;
    if (kc + 1 < 128) {
      const uint32_t qb = sb + (p ^ 1) * STAGE16_B;
      const int ko = (kc + 1) * 32;
#pragma unroll
      for (int i = 0; i < 4; i++) CP_ASYNC16(qb + ld_dst[i], ld_src[i] + ko);
      CP_COMMIT();
      CP_WAIT(1);
    } else {
      CP_WAIT(0);
    }
    __syncthreads();

    const uint32_t base = sb + p * STAGE16_B;
#pragma unroll
    for (int ks = 0; ks < 32; ks += 16) {
      uint32_t a4[2][4];
#pragma unroll
      for (int mt = 0; mt < 2; mt++)
        ldsm_x4(a4[mt], base + (m0 + mt * 16 + a_lrow) * 80 + (ks + a_lk) * 2);
      uint32_t b4[8][2];
#pragma unroll
      for (int nt2 = 0; nt2 < 4; nt2++) {
        uint32_t t0[4];
        ldsm_x4(t0, base + 10240 + (n0 + nt2 * 16 + b_lrow) * 80 + (ks + b_lk) * 2);
        b4[nt2 * 2][0] = t0[0]; b4[nt2 * 2][1] = t0[1];
        b4[nt2 * 2 + 1][0] = t0[2]; b4[nt2 * 2 + 1][1] = t0[3];
      }
#pragma unroll
      for (int mt = 0; mt < 2; mt++)
#pragma unroll
        for (int nt = 0; nt < 8; nt++)
          mma_f16(acc[mt][nt], a4[mt], b4[nt]);
    }
    __syncthreads();
  }

#pragma unroll
  for (int mt = 0; mt < 2; mt++)
#pragma unroll
    for (int nt = 0; nt < 8; nt++) {
      int m = row0 + m0 + mt * 16 + (lane >> 2);
      int n = col0 + n0 + nt * 8 + (lane & 3) * 2;
      *(float2*)&C[(size_t)m * Ntot + n] =
          make_float2(acc[mt][nt][0], acc[mt][nt][1]);
      *(float2*)&C[(size_t)(m + 8) * Ntot + n] =
          make_float2(acc[mt][nt][2], acc[mt][nt][3]);
    }
}

// ---------------------------------------------------------------------------
// Flash attention, all-fp16 mma (R10 config: synchronous K/V tile loads,
// 52KB smem -> 4 CTAs/SM).
// ---------------------------------------------------------------------------
#define FP 136
#define FLASH_SMEM (3 * 64 * FP * 2)

__global__ void __launch_bounds__(128) flash_mma_kernel(
    const __half* __restrict__ Q16, const __half* __restrict__ K16,
    const __half* __restrict__ V16, float* __restrict__ O) {
  extern __shared__ __align__(1024) char smem[];
  __half* Qs = (__half*)smem;
  __half* Ks = Qs + 64 * FP;
  __half* Vs = Qs + 2 * 64 * FP;

  const int h = blockIdx.y, kvh = h >> 2;
  const int qt = blockIdx.x, qbase = qt * 64;
  const int tid = threadIdx.x, w = tid >> 5, lane = tid & 31;
  const float scale = 0.08838834764831845f;

#pragma unroll
  for (int i = 0; i < 8; i++) {
    int idx = i * 128 + tid;
    int r = idx >> 4, c = idx & 15;
    *(float4*)&Qs[r * FP + c * 8] =
        *(const float4*)&Q16[(size_t)(qbase + r) * (NH * HD) + h * HD + c * 8];
  }
  __syncthreads();

  const uint32_t a_lrow = (lane & 7) + ((lane >> 3) & 1) * 8;
  const uint32_t a_lk   = ((lane >> 4) & 1) * 8;
  const uint32_t b_lrow = (lane & 7) + ((lane >> 4) & 1) * 8;
  const uint32_t b_lk   = ((lane >> 3) & 1) * 8;
  uint32_t qa[8][4];
  {
    uint32_t qsb = smem_u32(Qs);
#pragma unroll
    for (int ks = 0; ks < 8; ks++)
      ldsm_x4(qa[ks], qsb + ((w * 16 + a_lrow) * FP + ks * 16 + a_lk) * 2);
  }

  const int row0 = qbase + w * 16 + (lane >> 2);
  const int row1 = row0 + 8;

  float m_i[2] = {-1e30f, -1e30f}, l_i[2] = {0.f, 0.f};
  float o[16][4];
#pragma unroll
  for (int nt = 0; nt < 16; nt++)
#pragma unroll
    for (int j = 0; j < 4; j++) o[nt][j] = 0.f;

  const uint32_t ksb = smem_u32(Ks), vsb = smem_u32(Vs);

#pragma unroll 1
  for (int kt = 0; kt <= qt; kt++) {
    const int kbase = kt * 64;
    __syncthreads();
#pragma unroll
    for (int i = 0; i < 8; i++) {
      int idx = i * 128 + tid;
      int r = idx >> 4, c = idx & 15;
      size_t g = (size_t)(kbase + r) * (NKV * HD) + kvh * HD + c * 8;
      *(float4*)&Ks[r * FP + c * 8] = *(const float4*)&K16[g];
      *(float4*)&Vs[r * FP + c * 8] = *(const float4*)&V16[g];
    }
    __syncthreads();

    float s[8][4];
#pragma unroll
    for (int nt = 0; nt < 8; nt++)
#pragma unroll
      for (int j = 0; j < 4; j++) s[nt][j] = 0.f;
#pragma unroll
    for (int np = 0; np < 4; np++) {
#pragma unroll
      for (int ks = 0; ks < 8; ks++) {
        uint32_t kb[4];
        ldsm_x4(kb, ksb + ((np * 16 + b_lrow) * FP + ks * 16 + b_lk) * 2);
        mma_f16(s[np * 2],     qa[ks], kb);
        mma_f16(s[np * 2 + 1], qa[ks], kb + 2);
      }
    }

    float rm0 = -1e30f, rm1 = -1e30f;
    const bool diag = (kt == qt);
#pragma unroll
    for (int nt = 0; nt < 8; nt++) {
      int c0 = kbase + nt * 8 + (lane & 3) * 2;
#pragma unroll
      for (int j = 0; j < 4; j++) s[nt][j] *= scale;
      if (diag) {
        if (c0     > row0) s[nt][0] = -1e30f;
        if (c0 + 1 > row0) s[nt][1] = -1e30f;
        if (c0     > row1) s[nt][2] = -1e30f;
        if (c0 + 1 > row1) s[nt][3] = -1e30f;
      }
      rm0 = fmaxf(rm0, fmaxf(s[nt][0], s[nt][1]));
      rm1 = fmaxf(rm1, fmaxf(s[nt][2], s[nt][3]));
    }
#pragma unroll
    for (int off = 1; off <= 2; off <<= 1) {
      rm0 = fmaxf(rm0, __shfl_xor_sync(0xffffffffu, rm0, off));
      rm1 = fmaxf(rm1, __shfl_xor_sync(0xffffffffu, rm1, off));
    }
    float mn0 = fmaxf(m_i[0], rm0), mn1 = fmaxf(m_i[1], rm1);
    float cor0 = __expf(m_i[0] - mn0), cor1 = __expf(m_i[1] - mn1);
    float rs0 = 0.f, rs1 = 0.f;
#pragma unroll
    for (int nt = 0; nt < 8; nt++) {
      s[nt][0] = __expf(s[nt][0] - mn0); rs0 += s[nt][0];
      s[nt][1] = __expf(s[nt][1] - mn0); rs0 += s[nt][1];
      s[nt][2] = __expf(s[nt][2] - mn1); rs1 += s[nt][2];
      s[nt][3] = __expf(s[nt][3] - mn1); rs1 += s[nt][3];
    }
#pragma unroll
    for (int off = 1; off <= 2; off <<= 1) {
      rs0 += __shfl_xor_sync(0xffffffffu, rs0, off);
      rs1 += __shfl_xor_sync(0xffffffffu, rs1, off);
    }
    l_i[0] = l_i[0] * cor0 + rs0; m_i[0] = mn0;
    l_i[1] = l_i[1] * cor1 + rs1; m_i[1] = mn1;
#pragma unroll
    for (int nt = 0; nt < 16; nt++) {
      o[nt][0] *= cor0; o[nt][1] *= cor0;
      o[nt][2] *= cor1; o[nt][3] *= cor1;
    }

    // PV: single-pass fp16
#pragma unroll
    for (int kk = 0; kk < 4; kk++) {
      float* p0 = s[kk * 2];
      float* p1 = s[kk * 2 + 1];
      uint32_t ph[4];
      ph[0] = pkhf(p0[0], p0[1]); ph[1] = pkhf(p0[2], p0[3]);
      ph[2] = pkhf(p1[0], p1[1]); ph[3] = pkhf(p1[2], p1[3]);

      uint32_t vro = ((kk * 16 + (lane & 15)) * FP + ((lane >> 4) << 3)) * 2;
#pragma unroll
      for (int ntp = 0; ntp < 8; ntp++) {
        uint32_t v4[4];
        ldsm_x4_t(v4, vsb + vro + ntp * 32);
        mma_f16(o[ntp * 2],     ph, v4);
        mma_f16(o[ntp * 2 + 1], ph, v4 + 2);
      }
    }
  }

  float rl0 = 1.0f / l_i[0], rl1 = 1.0f / l_i[1];
#pragma unroll
  for (int nt = 0; nt < 16; nt++) {
    int col = h * HD + nt * 8 + (lane & 3) * 2;
    *(float2*)&O[(size_t)row0 * (NH * HD) + col] =
        make_float2(o[nt][0] * rl0, o[nt][1] * rl0);
    *(float2*)&O[(size_t)row1 * (NH * HD) + col] =
        make_float2(o[nt][2] * rl1, o[nt][3] * rl1);
  }
}

// ---------------------------------------------------------------------------
// Host launcher
// ---------------------------------------------------------------------------
extern "C" void kernel_launch(void* const* d_in, const int* in_sizes, int n_in,
                              void* d_out, int out_size) {
  const float* hidden = (const float*)d_in[0];
  const float* Wq = (const float*)d_in[1];
  const float* Wk = (const float*)d_in[2];
  const float* Wv = (const float*)d_in[3];
  const float* Wo = (const float*)d_in[4];
  const float* cosp = (const float*)d_in[5];
  const float* sinp = (const float*)d_in[6];
  const int* qcol = (const int*)d_in[8];
  const int* qrow = (const int*)d_in[9];
  const int* kcol = (const int*)d_in[10];
  const int* krow = (const int*)d_in[11];
  const int* vcol = (const int*)d_in[12];
  const int* vrow = (const int*)d_in[13];
  const int* ocol = (const int*)d_in[14];
  const int* orow = (const int*)d_in[15];

  __half *hq16, *hk16, *hv16, *wq16, *wk16, *wv16, *wo16, *ao16;
  __half *Q16, *K16, *V16;
  float *Ab;
  cudaGetSymbolAddress((void**)&hq16, g_hq16);
  cudaGetSymbolAddress((void**)&hk16, g_hk16);
  cudaGetSymbolAddress((void**)&hv16, g_hv16);
  cudaGetSymbolAddress((void**)&wq16, g_wq16);
  cudaGetSymbolAddress((void**)&wk16, g_wk16);
  cudaGetSymbolAddress((void**)&wv16, g_wv16);
  cudaGetSymbolAddress((void**)&wo16, g_wo16);
  cudaGetSymbolAddress((void**)&ao16, g_ao16);
  cudaGetSymbolAddress((void**)&Ab, g_A);
  cudaGetSymbolAddress((void**)&Q16, g_Q16);
  cudaGetSymbolAddress((void**)&K16, g_K16);
  cudaGetSymbolAddress((void**)&V16, g_V16);

  cudaFuncSetAttribute(gemm16_qkv_kernel,
                       cudaFuncAttributeMaxDynamicSharedMemorySize, GEMM16_SMEM);
  cudaFuncSetAttribute(gemm16_mma_kernel,
                       cudaFuncAttributeMaxDynamicSharedMemorySize, GEMM16_SMEM);
  cudaFuncSetAttribute(flash_mma_kernel,
                       cudaFuncAttributeMaxDynamicSharedMemorySize, FLASH_SMEM);

  // Fused QKV gather + fp16 convert (one pass over hidden)
  gather3_convert_kernel<<<SEQ, 256>>>(hidden, qcol, kcol, vcol,
                                       hq16, hk16, hv16);

  // All weight converts in one launch (one block per row)
  wconvert_all_kernel<<<10240, 256>>>(
      Wq, Wk, Wv, Wo, qrow, krow, vrow, orow, wq16, wk16, wv16, wo16);

  // Q + K + V projections, rope/convert fused into epilogue, ONE launch
  gemm16_qkv_kernel<<<768, 256, GEMM16_SMEM>>>(
      hq16, hk16, hv16, wq16, wk16, wv16, cosp, sinp, Q16, K16, V16);

  flash_mma_kernel<<<dim3(SEQ / 64, NH), 128, FLASH_SMEM>>>(Q16, K16, V16, Ab);

  // O path: gather+fp16, single-pass fp16 GEMM (fp32 out)
  gather1_convert_kernel<<<SEQ, 256>>>(Ab, ocol, ao16);
  gemm16_mma_kernel<<<dim3(16, 32), 256, GEMM16_SMEM>>>(
      ao16, wo16, (float*)d_out, 4096);
}